// round 16
// baseline (speedup 1.0000x reference)
#include <cuda_runtime.h>
#include <cuda_fp16.h>
#include <cstdint>
#include <math.h>

#define N_PTS 20000
#define M_PTS 160000
#define CI 128
#define CO 64
#define GD 34
#define GSZ (GD*GD*GD)

// stage: A 256x64 fp16 (row pad 72 halves = 144B), B 64x64 fp16 (same pad)
#define A_PAD 72
#define SMEM_A_BYTES (256*A_PAD*2)     // 36864
#define SMEM_B_BYTES (64*A_PAD*2)      // 9216
#define STG_BYTES (SMEM_A_BYTES + SMEM_B_BYTES)   // 46080
#define SMEM_DYN (2*STG_BYTES)                     // 92160

// ---------------- device scratch ----------------
__device__ int    g_pgrid[GSZ];
__device__ __align__(16) __half g_h_h[N_PTS*CI];       // silu(gn1(x)) fp16
__device__ float  g_skip[N_PTS*CO];
__device__ __align__(16) __half g_mid_h[M_PTS*CO];     // conv1 out (fp16 storage; stats fp32-exact)
__device__ __align__(16) __half g_act_h[M_PTS*CO];     // silu(gn2(mid)) fp16
__device__ __align__(16) __half g_weffT_h[8*8*CO*CI];  // [o][n][cout][cin]
__device__ __align__(16) __half g_w2t_h[27*CO*CO];     // [tap][cout][cin]
__device__ float g_sum1[CI], g_sq1[CI];
__device__ float g_sum2[CO], g_sq2[CO];

// ---------------- helpers ----------------
__device__ __forceinline__ uint32_t smem_u32(const void* p){
    uint32_t a;
    asm("{ .reg .u64 t; cvta.to.shared.u64 t, %1; cvt.u32.u64 %0, t; }" : "=r"(a) : "l"(p));
    return a;
}
// .cg: L2-only on the read path — L1 fills buy nothing (L2=13%) but cost L1 pipe (our top pipe)
__device__ __forceinline__ void cp_async16(uint32_t dst, const void* src, int src_size){
    asm volatile("cp.async.cg.shared.global [%0], [%1], 16, %2;"
                 :: "r"(dst), "l"(src), "r"(src_size) : "memory");
}
#define CP_COMMIT() asm volatile("cp.async.commit_group;" ::: "memory")
#define CP_WAIT(n)  asm volatile("cp.async.wait_group %0;" :: "n"(n) : "memory")

__device__ __forceinline__ void ldsm4(uint32_t* r, uint32_t addr){
    asm volatile("ldmatrix.sync.aligned.m8n8.x4.shared.b16 {%0,%1,%2,%3}, [%4];"
        : "=r"(r[0]),"=r"(r[1]),"=r"(r[2]),"=r"(r[3]) : "r"(addr));
}
__device__ __forceinline__ void mma16816(float* d, const uint32_t* a, uint32_t b0, uint32_t b1){
    asm volatile("mma.sync.aligned.m16n8k16.row.col.f32.f16.f16.f32 "
        "{%0,%1,%2,%3}, {%4,%5,%6,%7}, {%8,%9}, {%0,%1,%2,%3};"
        : "+f"(d[0]),"+f"(d[1]),"+f"(d[2]),"+f"(d[3])
        : "r"(a[0]),"r"(a[1]),"r"(a[2]),"r"(a[3]), "r"(b0),"r"(b1));
}

// ---------------- kernel 1: init ----------------
__global__ void k_init(){
    int i = blockIdx.x*256 + threadIdx.x;
    if (i < GSZ) g_pgrid[i] = -1;
    if (i < CI){ g_sum1[i]=0.f; g_sq1[i]=0.f; }
    if (i < CO){ g_sum2[i]=0.f; g_sq2[i]=0.f; }
}

// ---------------- kernel 2: scatter + stats1 ----------------
__global__ void k_front(const int* __restrict__ coords, const float* __restrict__ xf){
    int b = blockIdx.x, t = threadIdx.x;
    if (b < 79){
        int p = b*256 + t;
        if (p < N_PTS){
            int x=coords[p*4+1], y=coords[p*4+2], z=coords[p*4+3];
            g_pgrid[((x+1)*GD + (y+1))*GD + (z+1)] = p;
        }
    } else {
        int bi = b - 79;                 // 0..159
        int c = t & 127;
        int sId = bi + 160*(t>>7);       // 0..319
        float s=0.f, s2=0.f;
        for (int r = sId; r < N_PTS; r += 320){
            float v = xf[r*CI + c]; s += v; s2 += v*v;
        }
        atomicAdd(&g_sum1[c], s); atomicAdd(&g_sq1[c], s2);
    }
}

// ---------------- kernel 3: prep = weffT | w2t | h(+fin1 inline) ----------------
__global__ void k_prep(const float* __restrict__ W1, const float* __restrict__ W2,
                       const float* __restrict__ xf,
                       const float* __restrict__ gma, const float* __restrict__ bta){
    int b = blockIdx.x, t = threadIdx.x;
    if (b < 2048){
        int idx = b*256 + t;   // 8*8*128*64
        int cout = idx & 63, cin = (idx>>6)&127, n = (idx>>13)&7, o = idx>>16;
        int d0=(o>>2)&1, d1=(o>>1)&1, d2=o&1;
        int n0=(n>>2)&1, n1=(n>>1)&1, n2=n&1;
        float s = 0.f;
        for (int i=0;i<3;i++){
            int t0=d0+i-1; int p0=(t0>=2)?1:((t0>=0)?0:-1);
            if (p0 - d0 + 1 != n0) continue;
            for (int j=0;j<3;j++){
                int t1=d1+j-1; int p1=(t1>=2)?1:((t1>=0)?0:-1);
                if (p1 - d1 + 1 != n1) continue;
                for (int k=0;k<3;k++){
                    int t2=d2+k-1; int p2=(t2>=2)?1:((t2>=0)?0:-1);
                    if (p2 - d2 + 1 != n2) continue;
                    s += W1[(((i*3+j)*3+k)*CI + cin)*CO + cout];
                }
            }
        }
        g_weffT_h[((o*8+n)*CO + cout)*CI + cin] = __float2half(s);
    } else if (b < 2480){
        int idx = (b-2048)*256 + t;   // 27*64*64 = 110592
        if (idx < 27*CO*CO){
            int cout = idx & 63, cin = (idx>>6)&63, tap = idx>>12;
            g_w2t_h[(tap*CO + cout)*CO + cin] = __float2half(W2[(tap*CO + cin)*CO + cout]);
        }
    } else {
        __shared__ float smu[32], srs[32];
        if (t < 32){
            float s=0.f, s2=0.f;
            #pragma unroll
            for (int j=0;j<4;j++){ s += g_sum1[t*4+j]; s2 += g_sq1[t*4+j]; }
            float inv = 1.f/(float)(N_PTS*4);
            float mu = s*inv, var = s2*inv - mu*mu;
            smu[t] = mu; srs[t] = rsqrtf(var + 1e-5f);
        }
        __syncthreads();
        int i = (b-2480)*256 + t;     // N_PTS*CI = 2560000, 10000 blocks exact
        int c = i & (CI-1); int g = c >> 2;
        float v = (xf[i] - smu[g])*srs[g]*gma[c] + bta[c];
        v = v / (1.f + expf(-v));
        g_h_h[i] = __float2half(v);
    }
}

// ---------------- skip tile (device fn, fp32 FFMA; runs in conv1 grid y==8) ----------------
__device__ __forceinline__ void mma_row(float4 a, float4 w0, float4 w1, float4 w2, float4 w3,
                                        float acc[4]){
    acc[0]=fmaf(a.x,w0.x,acc[0]); acc[0]=fmaf(a.y,w1.x,acc[0]); acc[0]=fmaf(a.z,w2.x,acc[0]); acc[0]=fmaf(a.w,w3.x,acc[0]);
    acc[1]=fmaf(a.x,w0.y,acc[1]); acc[1]=fmaf(a.y,w1.y,acc[1]); acc[1]=fmaf(a.z,w2.y,acc[1]); acc[1]=fmaf(a.w,w3.y,acc[1]);
    acc[2]=fmaf(a.x,w0.z,acc[2]); acc[2]=fmaf(a.y,w1.z,acc[2]); acc[2]=fmaf(a.z,w2.z,acc[2]); acc[2]=fmaf(a.w,w3.z,acc[2]);
    acc[3]=fmaf(a.x,w0.w,acc[3]); acc[3]=fmaf(a.y,w1.w,acc[3]); acc[3]=fmaf(a.z,w2.w,acc[3]); acc[3]=fmaf(a.w,w3.w,acc[3]);
}
__device__ void skip_tile(const float* __restrict__ xf, const float* __restrict__ Ws,
                          const float* __restrict__ bs, int p0, int t, char* dyn){
    float (*A_s)[68] = (float(*)[68])dyn;
    float (*W_s)[68] = (float(*)[68])(dyn + 64*68*4);
    float acc[4][4] = {};
    int tr = t>>4, tc = t&15;
    for (int ck = 0; ck < 2; ck++){
        __syncthreads();
        #pragma unroll
        for (int rep = 0; rep < 4; rep++){
            int idx = rep*256 + t;
            int r = idx>>4, kv = idx&15;
            int p = p0 + r;
            float4 v = make_float4(0.f,0.f,0.f,0.f);
            if (p < N_PTS) v = *(const float4*)&xf[p*CI + ck*64 + kv*4];
            *(float4*)&A_s[r][kv*4] = v;
            *(float4*)&W_s[r][kv*4] = *(const float4*)&Ws[(ck*64 + r)*CO + kv*4];
        }
        __syncthreads();
        #pragma unroll
        for (int kk = 0; kk < 64; kk += 4){
            float4 w0 = *(float4*)&W_s[kk+0][tc*4];
            float4 w1 = *(float4*)&W_s[kk+1][tc*4];
            float4 w2 = *(float4*)&W_s[kk+2][tc*4];
            float4 w3 = *(float4*)&W_s[kk+3][tc*4];
            #pragma unroll
            for (int i = 0; i < 4; i++){
                float4 a = *(float4*)&A_s[tr*4+i][kk];
                mma_row(a, w0, w1, w2, w3, acc[i]);
            }
        }
    }
    #pragma unroll
    for (int i = 0; i < 4; i++){
        int p = p0 + tr*4 + i;
        if (p < N_PTS){
            float4 r;
            r.x = acc[i][0] + bs[tc*4+0];
            r.y = acc[i][1] + bs[tc*4+1];
            r.z = acc[i][2] + bs[tc*4+2];
            r.w = acc[i][3] + bs[tc*4+3];
            *(float4*)&g_skip[p*CO + tc*4] = r;
        }
    }
}

// ---------------- MMA on one staged chunk: A[256][64] x B^T[64][64] fp16 ----------------
// Lane mapping (A and B): lanes 0-15 -> rows +0..15 at col base; lanes 16-31 -> same rows
// at col base +16B. ldsm4 regs: [ (r0-7,k0-7), (r8-15,k0-7), (r0-7,k8-15), (r8-15,k8-15) ]
// => B n8-fragments pair {b[0],b[2]} and {b[1],b[3]}.
__device__ __forceinline__ void mma_chunk256(uint32_t bA, uint32_t bB, int l, int w,
                                             float acc[16][4]){
    int mi = w>>1, ni = w&1;
    int lr = l&15, lc = l>>4;
    #pragma unroll
    for (int ks = 0; ks < 4; ks++){
        int colb = ks*32 + lc*16;
        uint32_t a[4][4];
        #pragma unroll
        for (int mt = 0; mt < 4; mt++){
            int row = mi*64 + mt*16 + lr;
            ldsm4(a[mt], bA + row*(A_PAD*2) + colb);
        }
        #pragma unroll
        for (int bt = 0; bt < 2; bt++){
            uint32_t b[4];
            int brow = ni*32 + bt*16 + lr;
            ldsm4(b, bB + brow*(A_PAD*2) + colb);
            #pragma unroll
            for (int mt = 0; mt < 4; mt++){
                mma16816(acc[mt*4 + bt*2],     a[mt], b[0], b[2]);
                mma16816(acc[mt*4 + bt*2 + 1], a[mt], b[1], b[3]);
            }
        }
    }
}

// ---------------- kernel 4: conv1 (+ skip on y==8, + stats2 in epilogue) ----------------
__device__ __forceinline__ void conv1_issue(int st, int o, const int* s_nbr, int t, char* dyn){
    int n = st>>1, ck = st&1;
    char* base = dyn + (st&1)*STG_BYTES;
    uint32_t bA = smem_u32(base);
    uint32_t bB = smem_u32(base + SMEM_A_BYTES);
    int rr = t>>3, c8 = t&7;
    #pragma unroll
    for (int it = 0; it < 8; it++){
        int r = it*32 + rr;
        int nb = s_nbr[n*256 + r];
        const __half* src = (nb >= 0) ? &g_h_h[nb*CI + ck*64 + c8*8] : g_h_h;
        cp_async16(bA + r*(A_PAD*2) + c8*16, src, (nb >= 0) ? 16 : 0);
    }
    #pragma unroll
    for (int it = 0; it < 2; it++){
        int r = it*32 + rr;
        cp_async16(bB + r*(A_PAD*2) + c8*16,
                   &g_weffT_h[((o*8+n)*CO + r)*CI + ck*64 + c8*8], 16);
    }
    CP_COMMIT();
}

__global__ __launch_bounds__(256,2) void k_conv1_mma(const int* __restrict__ coords,
                                                     const float* __restrict__ b1,
                                                     const float* __restrict__ xf,
                                                     const float* __restrict__ Ws,
                                                     const float* __restrict__ bs){
    extern __shared__ __align__(16) char dyn[];
    __shared__ int s_nbr[8*256];
    int t = threadIdx.x, l = t&31, w = t>>5;

    if (blockIdx.y == 8){   // skip GEMM filler: 79 blocks x 256 rows
        #pragma unroll
        for (int c = 0; c < 4; c++)
            skip_tile(xf, Ws, bs, blockIdx.x*256 + c*64, t, dyn);
        return;
    }

    int p0 = blockIdx.x*256;
    int o  = blockIdx.y;
    int dx=(o>>2)&1, dy=(o>>1)&1, dz=o&1;

    {
        int p = p0 + t;
        if (p < N_PTS){
            int x=coords[p*4+1], y=coords[p*4+2], z=coords[p*4+3];
            #pragma unroll
            for (int n = 0; n < 8; n++){
                int ox = dx-1+((n>>2)&1), oy = dy-1+((n>>1)&1), oz = dz-1+(n&1);
                s_nbr[n*256 + t] = g_pgrid[((x+ox+1)*GD + (y+oy+1))*GD + (z+oz+1)];
            }
        } else {
            #pragma unroll
            for (int n = 0; n < 8; n++) s_nbr[n*256 + t] = -1;
        }
    }
    __syncthreads();

    conv1_issue(0, o, s_nbr, t, dyn);

    float acc[16][4] = {};
    for (int st = 0; st < 16; st++){
        CP_WAIT(0);
        __syncthreads();
        if (st + 1 < 16) conv1_issue(st+1, o, s_nbr, t, dyn);
        char* base = dyn + (st&1)*STG_BYTES;
        mma_chunk256(smem_u32(base), smem_u32(base + SMEM_A_BYTES), l, w, acc);
    }

    int mi = w>>1, ni = w&1;
    float s[8] = {}, s2[8] = {};
    #pragma unroll
    for (int mt = 0; mt < 4; mt++){
        #pragma unroll
        for (int nt = 0; nt < 4; nt++){
            float* ac = acc[mt*4+nt];
            int row0 = mi*64 + mt*16 + (l>>2);
            int col  = ni*32 + nt*8 + (l&3)*2;
            int p_0 = p0 + row0;
            if (p_0 < N_PTS){
                float vx = ac[0] + b1[col], vy = ac[1] + b1[col+1];
                *(__half2*)&g_mid_h[((size_t)p_0*8 + o)*CO + col] = __floats2half2_rn(vx, vy);
                s[nt*2+0] += vx; s2[nt*2+0] += vx*vx;
                s[nt*2+1] += vy; s2[nt*2+1] += vy*vy;
            }
            int p_1 = p0 + row0 + 8;
            if (p_1 < N_PTS){
                float vx = ac[2] + b1[col], vy = ac[3] + b1[col+1];
                *(__half2*)&g_mid_h[((size_t)p_1*8 + o)*CO + col] = __floats2half2_rn(vx, vy);
                s[nt*2+0] += vx; s2[nt*2+0] += vx*vx;
                s[nt*2+1] += vy; s2[nt*2+1] += vy*vy;
            }
        }
    }
    #pragma unroll
    for (int off = 4; off < 32; off <<= 1){
        #pragma unroll
        for (int j = 0; j < 8; j++){
            s[j]  += __shfl_xor_sync(0xffffffffu, s[j],  off);
            s2[j] += __shfl_xor_sync(0xffffffffu, s2[j], off);
        }
    }
    if (l < 4){
        #pragma unroll
        for (int j = 0; j < 8; j++){
            int col = ni*32 + (j>>1)*8 + l*2 + (j&1);
            atomicAdd(&g_sum2[col], s[j]);
            atomicAdd(&g_sq2[col],  s2[j]);
        }
    }
}

// ---------------- kernel 5: act (+fin2 inline), __half2 pairs ----------------
// cols (2j, 2j+1) share group g=j, so one mu/rs per half2.
__global__ void k_act(const float* __restrict__ gma, const float* __restrict__ bta){
    __shared__ float smu[32], srs[32];
    int t = threadIdx.x;
    if (t < 32){
        float s  = g_sum2[2*t] + g_sum2[2*t+1];
        float s2 = g_sq2[2*t]  + g_sq2[2*t+1];
        float inv = 1.f/(float)(M_PTS*2);
        float mu = s*inv, var = s2*inv - mu*mu;
        smu[t] = mu; srs[t] = rsqrtf(var + 1e-5f);
    }
    __syncthreads();
    int i2 = blockIdx.x*256 + t;           // half2 index; total M_PTS*32
    int c2 = i2 & 31;                       // col pair -> group
    float2 m = __half22float2(*(const __half2*)&g_mid_h[(size_t)i2*2]);
    float mu = smu[c2], rs = srs[c2];
    float vx = (m.x - mu)*rs*gma[c2*2]   + bta[c2*2];
    float vy = (m.y - mu)*rs*gma[c2*2+1] + bta[c2*2+1];
    vx = vx / (1.f + expf(-vx));
    vy = vy / (1.f + expf(-vy));
    *(__half2*)&g_act_h[(size_t)i2*2] = __floats2half2_rn(vx, vy);
}

// ---------------- kernel 6: conv2 ----------------
__device__ __forceinline__ void conv2_issue(int tap, const int* s_pnbr, int t, char* dyn){
    char* base = dyn + (tap&1)*STG_BYTES;
    uint32_t bA = smem_u32(base);
    uint32_t bB = smem_u32(base + SMEM_A_BYTES);
    int rr = t>>3, c8 = t&7;
    int o = rr & 7;
    int tx = tap/9, ty = (tap/3)%3, tz = tap%3;
    int sx = ((o>>2)&1) + tx - 1, sy = ((o>>1)&1) + ty - 1, sz = (o&1) + tz - 1;
    int n3 = ((sx>>1)+1)*9 + ((sy>>1)+1)*3 + ((sz>>1)+1);
    int par = (sx&1)*4 + (sy&1)*2 + (sz&1);
    #pragma unroll
    for (int it = 0; it < 8; it++){
        int r = it*32 + rr;
        int pi = r>>3;
        int q = s_pnbr[pi*27 + n3];
        int nb = (q >= 0) ? q*8 + par : -1;
        const __half* src = (nb >= 0) ? &g_act_h[nb*CO + c8*8] : g_act_h;
        cp_async16(bA + r*(A_PAD*2) + c8*16, src, (nb >= 0) ? 16 : 0);
    }
    #pragma unroll
    for (int it = 0; it < 2; it++){
        int r = it*32 + rr;
        cp_async16(bB + r*(A_PAD*2) + c8*16, &g_w2t_h[(tap*CO + r)*CO + c8*8], 16);
    }
    CP_COMMIT();
}

__global__ __launch_bounds__(256,2) void k_conv2_mma(const int* __restrict__ coords,
                                                     const float* __restrict__ b2,
                                                     float* __restrict__ out){
    extern __shared__ __align__(16) char dyn[];
    __shared__ int s_pnbr[32*27];
    int t = threadIdx.x, l = t&31, w = t>>5;
    int m0 = blockIdx.x*256;
    int pbase = m0 >> 3;

    for (int e = t; e < 32*27; e += 256){
        int pl = e/27, n3 = e - pl*27;
        int p = pbase + pl;
        int ox = n3/9 - 1, oy = (n3/3)%3 - 1, oz = n3%3 - 1;
        int x = coords[p*4+1], y = coords[p*4+2], z = coords[p*4+3];
        s_pnbr[e] = g_pgrid[((x+ox+1)*GD + (y+oy+1))*GD + (z+oz+1)];
    }
    __syncthreads();

    conv2_issue(0, s_pnbr, t, dyn);

    float acc[16][4] = {};
    for (int tap = 0; tap < 27; tap++){
        CP_WAIT(0);
        __syncthreads();
        if (tap + 1 < 27) conv2_issue(tap+1, s_pnbr, t, dyn);
        char* base = dyn + (tap&1)*STG_BYTES;
        mma_chunk256(smem_u32(base), smem_u32(base + SMEM_A_BYTES), l, w, acc);
    }

    int mi = w>>1, ni = w&1;
    #pragma unroll
    for (int mt = 0; mt < 4; mt++){
        #pragma unroll
        for (int nt = 0; nt < 4; nt++){
            float* ac = acc[mt*4+nt];
            int row0 = mi*64 + mt*16 + (l>>2);
            int col  = ni*32 + nt*8 + (l&3)*2;
            {
                int m = m0 + row0, p = m>>3;
                float2 v;
                v.x = ac[0] + b2[col]   + g_skip[p*CO + col];
                v.y = ac[1] + b2[col+1] + g_skip[p*CO + col+1];
                *(float2*)&out[(size_t)m*CO + col] = v;
            }
            {
                int m = m0 + row0 + 8, p = m>>3;
                float2 v;
                v.x = ac[2] + b2[col]   + g_skip[p*CO + col];
                v.y = ac[3] + b2[col+1] + g_skip[p*CO + col+1];
                *(float2*)&out[(size_t)m*CO + col] = v;
            }
        }
    }
}

// ---------------- launch ----------------
extern "C" void kernel_launch(void* const* d_in, const int* in_sizes, int n_in,
                              void* d_out, int out_size){
    const float* xf    = (const float*)d_in[0];
    const int*   coords= (const int*)  d_in[1];
    const float* gn1g  = (const float*)d_in[2];
    const float* gn1b  = (const float*)d_in[3];
    const float* W1    = (const float*)d_in[4];
    const float* b1    = (const float*)d_in[5];
    const float* gn2g  = (const float*)d_in[6];
    const float* gn2b  = (const float*)d_in[7];
    const float* W2    = (const float*)d_in[8];
    const float* b2    = (const float*)d_in[9];
    const float* Ws    = (const float*)d_in[10];
    const float* bs    = (const float*)d_in[11];
    float* out = (float*)d_out;

    static int attr_done = 0;
    if (!attr_done){
        cudaFuncSetAttribute(k_conv1_mma, cudaFuncAttributeMaxDynamicSharedMemorySize, SMEM_DYN);
        cudaFuncSetAttribute(k_conv2_mma, cudaFuncAttributeMaxDynamicSharedMemorySize, SMEM_DYN);
        attr_done = 1;
    }

    k_init<<<(GSZ+255)/256, 256>>>();
    k_front<<<239, 256>>>(coords, xf);
    k_prep<<<12480, 256>>>(W1, W2, xf, gn1g, gn1b);
    k_conv1_mma<<<dim3(79, 9), 256, SMEM_DYN>>>(coords, b1, xf, Ws, bs);
    k_act<<<M_PTS*CO/512, 256>>>(gn2g, gn2b);
    k_conv2_mma<<<M_PTS/256, 256, SMEM_DYN>>>(coords, b2, out);
}

// round 17
// speedup vs baseline: 1.4796x; 1.4796x over previous
#include <cuda_runtime.h>
#include <cuda_fp16.h>
#include <cstdint>
#include <math.h>

#define N_PTS 20000
#define M_PTS 160000
#define CI 128
#define CO 64
#define GD 34
#define GSZ (GD*GD*GD)

// stage: A 256x64 fp16 (row pad 72 halves = 144B), B 64x64 fp16 (same pad)
#define A_PAD 72
#define SMEM_A_BYTES (256*A_PAD*2)     // 36864
#define SMEM_B_BYTES (64*A_PAD*2)      // 9216
#define STG_BYTES (SMEM_A_BYTES + SMEM_B_BYTES)   // 46080
#define SMEM_DYN (2*STG_BYTES)                     // 92160

// ---------------- device scratch ----------------
__device__ int    g_pgrid[GSZ];
__device__ __align__(16) __half g_h_h[N_PTS*CI];       // silu(gn1(x)) fp16
__device__ float  g_skip[N_PTS*CO];
__device__ __align__(16) __half g_mid_h[M_PTS*CO];     // conv1 out (fp16 storage; stats fp32-exact)
__device__ __align__(16) __half g_act_h[M_PTS*CO];     // silu(gn2(mid)) fp16
__device__ __align__(16) __half g_weffT_h[8*8*CO*CI];  // [o][n][cout][cin]
__device__ __align__(16) __half g_w2t_h[27*CO*CO];     // [tap][cout][cin]
__device__ float g_sum1[CI], g_sq1[CI];
__device__ float g_sum2[CO], g_sq2[CO];

// ---------------- helpers ----------------
__device__ __forceinline__ uint32_t smem_u32(const void* p){
    uint32_t a;
    asm("{ .reg .u64 t; cvta.to.shared.u64 t, %1; cvt.u32.u64 %0, t; }" : "=r"(a) : "l"(p));
    return a;
}
// .ca (L1-allocating): gather rows have high cross-chunk/cross-CTA L1 reuse —
// R16 measured .cg costing +42% on conv1 (L1 hits became L2 round-trips).
__device__ __forceinline__ void cp_async16(uint32_t dst, const void* src, int src_size){
    asm volatile("cp.async.ca.shared.global [%0], [%1], 16, %2;"
                 :: "r"(dst), "l"(src), "r"(src_size) : "memory");
}
#define CP_COMMIT() asm volatile("cp.async.commit_group;" ::: "memory")
#define CP_WAIT(n)  asm volatile("cp.async.wait_group %0;" :: "n"(n) : "memory")

__device__ __forceinline__ void ldsm4(uint32_t* r, uint32_t addr){
    asm volatile("ldmatrix.sync.aligned.m8n8.x4.shared.b16 {%0,%1,%2,%3}, [%4];"
        : "=r"(r[0]),"=r"(r[1]),"=r"(r[2]),"=r"(r[3]) : "r"(addr));
}
__device__ __forceinline__ void mma16816(float* d, const uint32_t* a, uint32_t b0, uint32_t b1){
    asm volatile("mma.sync.aligned.m16n8k16.row.col.f32.f16.f16.f32 "
        "{%0,%1,%2,%3}, {%4,%5,%6,%7}, {%8,%9}, {%0,%1,%2,%3};"
        : "+f"(d[0]),"+f"(d[1]),"+f"(d[2]),"+f"(d[3])
        : "r"(a[0]),"r"(a[1]),"r"(a[2]),"r"(a[3]), "r"(b0),"r"(b1));
}

// ---------------- kernel 1: init ----------------
__global__ void k_init(){
    int i = blockIdx.x*256 + threadIdx.x;
    if (i < GSZ) g_pgrid[i] = -1;
    if (i < CI){ g_sum1[i]=0.f; g_sq1[i]=0.f; }
    if (i < CO){ g_sum2[i]=0.f; g_sq2[i]=0.f; }
}

// ---------------- kernel 2: scatter + stats1 ----------------
__global__ void k_front(const int* __restrict__ coords, const float* __restrict__ xf){
    int b = blockIdx.x, t = threadIdx.x;
    if (b < 79){
        int p = b*256 + t;
        if (p < N_PTS){
            int x=coords[p*4+1], y=coords[p*4+2], z=coords[p*4+3];
            g_pgrid[((x+1)*GD + (y+1))*GD + (z+1)] = p;
        }
    } else {
        int bi = b - 79;                 // 0..159
        int c = t & 127;
        int sId = bi + 160*(t>>7);       // 0..319
        float s=0.f, s2=0.f;
        for (int r = sId; r < N_PTS; r += 320){
            float v = xf[r*CI + c]; s += v; s2 += v*v;
        }
        atomicAdd(&g_sum1[c], s); atomicAdd(&g_sq1[c], s2);
    }
}

// ---------------- kernel 3: prep = weffT | w2t | h(+fin1 inline) ----------------
__global__ void k_prep(const float* __restrict__ W1, const float* __restrict__ W2,
                       const float* __restrict__ xf,
                       const float* __restrict__ gma, const float* __restrict__ bta){
    int b = blockIdx.x, t = threadIdx.x;
    if (b < 2048){
        int idx = b*256 + t;   // 8*8*128*64
        int cout = idx & 63, cin = (idx>>6)&127, n = (idx>>13)&7, o = idx>>16;
        int d0=(o>>2)&1, d1=(o>>1)&1, d2=o&1;
        int n0=(n>>2)&1, n1=(n>>1)&1, n2=n&1;
        float s = 0.f;
        for (int i=0;i<3;i++){
            int t0=d0+i-1; int p0=(t0>=2)?1:((t0>=0)?0:-1);
            if (p0 - d0 + 1 != n0) continue;
            for (int j=0;j<3;j++){
                int t1=d1+j-1; int p1=(t1>=2)?1:((t1>=0)?0:-1);
                if (p1 - d1 + 1 != n1) continue;
                for (int k=0;k<3;k++){
                    int t2=d2+k-1; int p2=(t2>=2)?1:((t2>=0)?0:-1);
                    if (p2 - d2 + 1 != n2) continue;
                    s += W1[(((i*3+j)*3+k)*CI + cin)*CO + cout];
                }
            }
        }
        g_weffT_h[((o*8+n)*CO + cout)*CI + cin] = __float2half(s);
    } else if (b < 2480){
        int idx = (b-2048)*256 + t;   // 27*64*64 = 110592
        if (idx < 27*CO*CO){
            int cout = idx & 63, cin = (idx>>6)&63, tap = idx>>12;
            g_w2t_h[(tap*CO + cout)*CO + cin] = __float2half(W2[(tap*CO + cin)*CO + cout]);
        }
    } else {
        __shared__ float smu[32], srs[32];
        if (t < 32){
            float s=0.f, s2=0.f;
            #pragma unroll
            for (int j=0;j<4;j++){ s += g_sum1[t*4+j]; s2 += g_sq1[t*4+j]; }
            float inv = 1.f/(float)(N_PTS*4);
            float mu = s*inv, var = s2*inv - mu*mu;
            smu[t] = mu; srs[t] = rsqrtf(var + 1e-5f);
        }
        __syncthreads();
        int i = (b-2480)*256 + t;     // N_PTS*CI = 2560000, 10000 blocks exact
        int c = i & (CI-1); int g = c >> 2;
        float v = (xf[i] - smu[g])*srs[g]*gma[c] + bta[c];
        v = v / (1.f + expf(-v));
        g_h_h[i] = __float2half(v);
    }
}

// ---------------- skip tile (device fn, fp32 FFMA; runs in conv1 grid y==8) ----------------
__device__ __forceinline__ void mma_row(float4 a, float4 w0, float4 w1, float4 w2, float4 w3,
                                        float acc[4]){
    acc[0]=fmaf(a.x,w0.x,acc[0]); acc[0]=fmaf(a.y,w1.x,acc[0]); acc[0]=fmaf(a.z,w2.x,acc[0]); acc[0]=fmaf(a.w,w3.x,acc[0]);
    acc[1]=fmaf(a.x,w0.y,acc[1]); acc[1]=fmaf(a.y,w1.y,acc[1]); acc[1]=fmaf(a.z,w2.y,acc[1]); acc[1]=fmaf(a.w,w3.y,acc[1]);
    acc[2]=fmaf(a.x,w0.z,acc[2]); acc[2]=fmaf(a.y,w1.z,acc[2]); acc[2]=fmaf(a.z,w2.z,acc[2]); acc[2]=fmaf(a.w,w3.z,acc[2]);
    acc[3]=fmaf(a.x,w0.w,acc[3]); acc[3]=fmaf(a.y,w1.w,acc[3]); acc[3]=fmaf(a.z,w2.w,acc[3]); acc[3]=fmaf(a.w,w3.w,acc[3]);
}
__device__ void skip_tile(const float* __restrict__ xf, const float* __restrict__ Ws,
                          const float* __restrict__ bs, int p0, int t, char* dyn){
    float (*A_s)[68] = (float(*)[68])dyn;
    float (*W_s)[68] = (float(*)[68])(dyn + 64*68*4);
    float acc[4][4] = {};
    int tr = t>>4, tc = t&15;
    for (int ck = 0; ck < 2; ck++){
        __syncthreads();
        #pragma unroll
        for (int rep = 0; rep < 4; rep++){
            int idx = rep*256 + t;
            int r = idx>>4, kv = idx&15;
            int p = p0 + r;
            float4 v = make_float4(0.f,0.f,0.f,0.f);
            if (p < N_PTS) v = *(const float4*)&xf[p*CI + ck*64 + kv*4];
            *(float4*)&A_s[r][kv*4] = v;
            *(float4*)&W_s[r][kv*4] = *(const float4*)&Ws[(ck*64 + r)*CO + kv*4];
        }
        __syncthreads();
        #pragma unroll
        for (int kk = 0; kk < 64; kk += 4){
            float4 w0 = *(float4*)&W_s[kk+0][tc*4];
            float4 w1 = *(float4*)&W_s[kk+1][tc*4];
            float4 w2 = *(float4*)&W_s[kk+2][tc*4];
            float4 w3 = *(float4*)&W_s[kk+3][tc*4];
            #pragma unroll
            for (int i = 0; i < 4; i++){
                float4 a = *(float4*)&A_s[tr*4+i][kk];
                mma_row(a, w0, w1, w2, w3, acc[i]);
            }
        }
    }
    #pragma unroll
    for (int i = 0; i < 4; i++){
        int p = p0 + tr*4 + i;
        if (p < N_PTS){
            float4 r;
            r.x = acc[i][0] + bs[tc*4+0];
            r.y = acc[i][1] + bs[tc*4+1];
            r.z = acc[i][2] + bs[tc*4+2];
            r.w = acc[i][3] + bs[tc*4+3];
            *(float4*)&g_skip[p*CO + tc*4] = r;
        }
    }
}

// ---------------- MMA on one staged chunk: A[256][64] x B^T[64][64] fp16 ----------------
// Lane mapping (A and B): lanes 0-15 -> rows +0..15 at col base; lanes 16-31 -> same rows
// at col base +16B. ldsm4 regs: [ (r0-7,k0-7), (r8-15,k0-7), (r0-7,k8-15), (r8-15,k8-15) ]
// => B n8-fragments pair {b[0],b[2]} and {b[1],b[3]}.
__device__ __forceinline__ void mma_chunk256(uint32_t bA, uint32_t bB, int l, int w,
                                             float acc[16][4]){
    int mi = w>>1, ni = w&1;
    int lr = l&15, lc = l>>4;
    #pragma unroll
    for (int ks = 0; ks < 4; ks++){
        int colb = ks*32 + lc*16;
        uint32_t a[4][4];
        #pragma unroll
        for (int mt = 0; mt < 4; mt++){
            int row = mi*64 + mt*16 + lr;
            ldsm4(a[mt], bA + row*(A_PAD*2) + colb);
        }
        #pragma unroll
        for (int bt = 0; bt < 2; bt++){
            uint32_t b[4];
            int brow = ni*32 + bt*16 + lr;
            ldsm4(b, bB + brow*(A_PAD*2) + colb);
            #pragma unroll
            for (int mt = 0; mt < 4; mt++){
                mma16816(acc[mt*4 + bt*2],     a[mt], b[0], b[2]);
                mma16816(acc[mt*4 + bt*2 + 1], a[mt], b[1], b[3]);
            }
        }
    }
}

// ---------------- kernel 4: conv1 (+ skip on y==8, + stats2 in epilogue) ----------------
__device__ __forceinline__ void conv1_issue(int st, int o, const int* s_nbr, int t, char* dyn){
    int n = st>>1, ck = st&1;
    char* base = dyn + (st&1)*STG_BYTES;
    uint32_t bA = smem_u32(base);
    uint32_t bB = smem_u32(base + SMEM_A_BYTES);
    int rr = t>>3, c8 = t&7;
    #pragma unroll
    for (int it = 0; it < 8; it++){
        int r = it*32 + rr;
        int nb = s_nbr[n*256 + r];
        const __half* src = (nb >= 0) ? &g_h_h[nb*CI + ck*64 + c8*8] : g_h_h;
        cp_async16(bA + r*(A_PAD*2) + c8*16, src, (nb >= 0) ? 16 : 0);
    }
    #pragma unroll
    for (int it = 0; it < 2; it++){
        int r = it*32 + rr;
        cp_async16(bB + r*(A_PAD*2) + c8*16,
                   &g_weffT_h[((o*8+n)*CO + r)*CI + ck*64 + c8*8], 16);
    }
    CP_COMMIT();
}

__global__ __launch_bounds__(256,2) void k_conv1_mma(const int* __restrict__ coords,
                                                     const float* __restrict__ b1,
                                                     const float* __restrict__ xf,
                                                     const float* __restrict__ Ws,
                                                     const float* __restrict__ bs){
    extern __shared__ __align__(16) char dyn[];
    __shared__ int s_nbr[8*256];
    int t = threadIdx.x, l = t&31, w = t>>5;

    if (blockIdx.y == 8){   // skip GEMM filler: 79 blocks x 256 rows
        #pragma unroll
        for (int c = 0; c < 4; c++)
            skip_tile(xf, Ws, bs, blockIdx.x*256 + c*64, t, dyn);
        return;
    }

    int p0 = blockIdx.x*256;
    int o  = blockIdx.y;
    int dx=(o>>2)&1, dy=(o>>1)&1, dz=o&1;

    {
        int p = p0 + t;
        if (p < N_PTS){
            int x=coords[p*4+1], y=coords[p*4+2], z=coords[p*4+3];
            #pragma unroll
            for (int n = 0; n < 8; n++){
                int ox = dx-1+((n>>2)&1), oy = dy-1+((n>>1)&1), oz = dz-1+(n&1);
                s_nbr[n*256 + t] = g_pgrid[((x+ox+1)*GD + (y+oy+1))*GD + (z+oz+1)];
            }
        } else {
            #pragma unroll
            for (int n = 0; n < 8; n++) s_nbr[n*256 + t] = -1;
        }
    }
    __syncthreads();

    conv1_issue(0, o, s_nbr, t, dyn);

    float acc[16][4] = {};
    for (int st = 0; st < 16; st++){
        CP_WAIT(0);
        __syncthreads();
        if (st + 1 < 16) conv1_issue(st+1, o, s_nbr, t, dyn);
        char* base = dyn + (st&1)*STG_BYTES;
        mma_chunk256(smem_u32(base), smem_u32(base + SMEM_A_BYTES), l, w, acc);
    }

    int mi = w>>1, ni = w&1;
    float s[8] = {}, s2[8] = {};
    #pragma unroll
    for (int mt = 0; mt < 4; mt++){
        #pragma unroll
        for (int nt = 0; nt < 4; nt++){
            float* ac = acc[mt*4+nt];
            int row0 = mi*64 + mt*16 + (l>>2);
            int col  = ni*32 + nt*8 + (l&3)*2;
            int p_0 = p0 + row0;
            if (p_0 < N_PTS){
                float vx = ac[0] + b1[col], vy = ac[1] + b1[col+1];
                *(__half2*)&g_mid_h[((size_t)p_0*8 + o)*CO + col] = __floats2half2_rn(vx, vy);
                s[nt*2+0] += vx; s2[nt*2+0] += vx*vx;
                s[nt*2+1] += vy; s2[nt*2+1] += vy*vy;
            }
            int p_1 = p0 + row0 + 8;
            if (p_1 < N_PTS){
                float vx = ac[2] + b1[col], vy = ac[3] + b1[col+1];
                *(__half2*)&g_mid_h[((size_t)p_1*8 + o)*CO + col] = __floats2half2_rn(vx, vy);
                s[nt*2+0] += vx; s2[nt*2+0] += vx*vx;
                s[nt*2+1] += vy; s2[nt*2+1] += vy*vy;
            }
        }
    }
    #pragma unroll
    for (int off = 4; off < 32; off <<= 1){
        #pragma unroll
        for (int j = 0; j < 8; j++){
            s[j]  += __shfl_xor_sync(0xffffffffu, s[j],  off);
            s2[j] += __shfl_xor_sync(0xffffffffu, s2[j], off);
        }
    }
    if (l < 4){
        #pragma unroll
        for (int j = 0; j < 8; j++){
            int col = ni*32 + (j>>1)*8 + l*2 + (j&1);
            atomicAdd(&g_sum2[col], s[j]);
            atomicAdd(&g_sq2[col],  s2[j]);
        }
    }
}

// ---------------- kernel 5: act (+fin2 inline), __half2 pairs ----------------
__global__ void k_act(const float* __restrict__ gma, const float* __restrict__ bta){
    __shared__ float smu[32], srs[32];
    int t = threadIdx.x;
    if (t < 32){
        float s  = g_sum2[2*t] + g_sum2[2*t+1];
        float s2 = g_sq2[2*t]  + g_sq2[2*t+1];
        float inv = 1.f/(float)(M_PTS*2);
        float mu = s*inv, var = s2*inv - mu*mu;
        smu[t] = mu; srs[t] = rsqrtf(var + 1e-5f);
    }
    __syncthreads();
    int i2 = blockIdx.x*256 + t;           // half2 index; total M_PTS*32
    int c2 = i2 & 31;                       // col pair -> group
    float2 m = __half22float2(*(const __half2*)&g_mid_h[(size_t)i2*2]);
    float mu = smu[c2], rs = srs[c2];
    float vx = (m.x - mu)*rs*gma[c2*2]   + bta[c2*2];
    float vy = (m.y - mu)*rs*gma[c2*2+1] + bta[c2*2+1];
    vx = vx / (1.f + expf(-vx));
    vy = vy / (1.f + expf(-vy));
    *(__half2*)&g_act_h[(size_t)i2*2] = __floats2half2_rn(vx, vy);
}

// ---------------- kernel 6: conv2 ----------------
__device__ __forceinline__ void conv2_issue(int tap, const int* s_pnbr, int t, char* dyn){
    char* base = dyn + (tap&1)*STG_BYTES;
    uint32_t bA = smem_u32(base);
    uint32_t bB = smem_u32(base + SMEM_A_BYTES);
    int rr = t>>3, c8 = t&7;
    int o = rr & 7;
    int tx = tap/9, ty = (tap/3)%3, tz = tap%3;
    int sx = ((o>>2)&1) + tx - 1, sy = ((o>>1)&1) + ty - 1, sz = (o&1) + tz - 1;
    int n3 = ((sx>>1)+1)*9 + ((sy>>1)+1)*3 + ((sz>>1)+1);
    int par = (sx&1)*4 + (sy&1)*2 + (sz&1);
    #pragma unroll
    for (int it = 0; it < 8; it++){
        int r = it*32 + rr;
        int pi = r>>3;
        int q = s_pnbr[pi*27 + n3];
        int nb = (q >= 0) ? q*8 + par : -1;
        const __half* src = (nb >= 0) ? &g_act_h[nb*CO + c8*8] : g_act_h;
        cp_async16(bA + r*(A_PAD*2) + c8*16, src, (nb >= 0) ? 16 : 0);
    }
    #pragma unroll
    for (int it = 0; it < 2; it++){
        int r = it*32 + rr;
        cp_async16(bB + r*(A_PAD*2) + c8*16, &g_w2t_h[(tap*CO + r)*CO + c8*8], 16);
    }
    CP_COMMIT();
}

__global__ __launch_bounds__(256,2) void k_conv2_mma(const int* __restrict__ coords,
                                                     const float* __restrict__ b2,
                                                     float* __restrict__ out){
    extern __shared__ __align__(16) char dyn[];
    __shared__ int s_pnbr[32*27];
    int t = threadIdx.x, l = t&31, w = t>>5;
    int m0 = blockIdx.x*256;
    int pbase = m0 >> 3;

    for (int e = t; e < 32*27; e += 256){
        int pl = e/27, n3 = e - pl*27;
        int p = pbase + pl;
        int ox = n3/9 - 1, oy = (n3/3)%3 - 1, oz = n3%3 - 1;
        int x = coords[p*4+1], y = coords[p*4+2], z = coords[p*4+3];
        s_pnbr[e] = g_pgrid[((x+ox+1)*GD + (y+oy+1))*GD + (z+oz+1)];
    }
    __syncthreads();

    conv2_issue(0, s_pnbr, t, dyn);

    float acc[16][4] = {};
    for (int tap = 0; tap < 27; tap++){
        CP_WAIT(0);
        __syncthreads();
        if (tap + 1 < 27) conv2_issue(tap+1, s_pnbr, t, dyn);
        char* base = dyn + (tap&1)*STG_BYTES;
        mma_chunk256(smem_u32(base), smem_u32(base + SMEM_A_BYTES), l, w, acc);
    }

    int mi = w>>1, ni = w&1;
    #pragma unroll
    for (int mt = 0; mt < 4; mt++){
        #pragma unroll
        for (int nt = 0; nt < 4; nt++){
            float* ac = acc[mt*4+nt];
            int row0 = mi*64 + mt*16 + (l>>2);
            int col  = ni*32 + nt*8 + (l&3)*2;
            {
                int m = m0 + row0, p = m>>3;
                float2 v;
                v.x = ac[0] + b2[col]   + g_skip[p*CO + col];
                v.y = ac[1] + b2[col+1] + g_skip[p*CO + col+1];
                *(float2*)&out[(size_t)m*CO + col] = v;
            }
            {
                int m = m0 + row0 + 8, p = m>>3;
                float2 v;
                v.x = ac[2] + b2[col]   + g_skip[p*CO + col];
                v.y = ac[3] + b2[col+1] + g_skip[p*CO + col+1];
                *(float2*)&out[(size_t)m*CO + col] = v;
            }
        }
    }
}

// ---------------- launch ----------------
extern "C" void kernel_launch(void* const* d_in, const int* in_sizes, int n_in,
                              void* d_out, int out_size){
    const float* xf    = (const float*)d_in[0];
    const int*   coords= (const int*)  d_in[1];
    const float* gn1g  = (const float*)d_in[2];
    const float* gn1b  = (const float*)d_in[3];
    const float* W1    = (const float*)d_in[4];
    const float* b1    = (const float*)d_in[5];
    const float* gn2g  = (const float*)d_in[6];
    const float* gn2b  = (const float*)d_in[7];
    const float* W2    = (const float*)d_in[8];
    const float* b2    = (const float*)d_in[9];
    const float* Ws    = (const float*)d_in[10];
    const float* bs    = (const float*)d_in[11];
    float* out = (float*)d_out;

    static int attr_done = 0;
    if (!attr_done){
        cudaFuncSetAttribute(k_conv1_mma, cudaFuncAttributeMaxDynamicSharedMemorySize, SMEM_DYN);
        cudaFuncSetAttribute(k_conv2_mma, cudaFuncAttributeMaxDynamicSharedMemorySize, SMEM_DYN);
        attr_done = 1;
    }

    k_init<<<(GSZ+255)/256, 256>>>();
    k_front<<<239, 256>>>(coords, xf);
    k_prep<<<12480, 256>>>(W1, W2, xf, gn1g, gn1b);
    k_conv1_mma<<<dim3(79, 9), 256, SMEM_DYN>>>(coords, b1, xf, Ws, bs);
    k_act<<<M_PTS*CO/512, 256>>>(gn2g, gn2b);
    k_conv2_mma<<<M_PTS/256, 256, SMEM_DYN>>>(coords, b2, out);
}